// round 10
// baseline (speedup 1.0000x reference)
#include <cuda_runtime.h>
#include <cuda_bf16.h>
#include <cstdint>
#include <cstddef>

#define N_QTOK 4096      // 128 query batches * 32 tokens
#define N_DTOK 16384     // 128 doc batches * 128 tokens
#define N_TOK  20480
#define DIM    128
#define HID    256
#define N_ETILE 320      // 20480 / 64 rows per embed tile

__device__ __align__(16) __nv_bfloat16 g_emb[(size_t)N_TOK * DIM];
__device__ __align__(16) __nv_bfloat16 g_Whi[HID * DIM];
__device__ __align__(16) __nv_bfloat16 g_Wlo[HID * DIM];
__device__ unsigned g_ctr  = 0;   // embed steal counter (reset at barrier 2)
__device__ unsigned gb1a = 0, gb1b = 0, gb2a = 0, gb2b = 0;

// ---------------------------------------------------------------------------
// PTX helpers (base sm_103 only — tcgen05 needs compute_103a virtual arch,
// which the harness does not use)
// ---------------------------------------------------------------------------
__device__ __forceinline__ void ldsm4(uint32_t& r0, uint32_t& r1,
                                      uint32_t& r2, uint32_t& r3, unsigned addr) {
    asm volatile("ldmatrix.sync.aligned.m8n8.x4.shared.b16 {%0,%1,%2,%3}, [%4];\n"
                 : "=r"(r0), "=r"(r1), "=r"(r2), "=r"(r3) : "r"(addr));
}
__device__ __forceinline__ void ldsm4t(uint32_t& r0, uint32_t& r1,
                                       uint32_t& r2, uint32_t& r3, unsigned addr) {
    asm volatile("ldmatrix.sync.aligned.m8n8.x4.trans.shared.b16 {%0,%1,%2,%3}, [%4];\n"
                 : "=r"(r0), "=r"(r1), "=r"(r2), "=r"(r3) : "r"(addr));
}
__device__ __forceinline__ void mma16816(float* c, const uint32_t* a,
                                         uint32_t b0, uint32_t b1) {
    asm volatile(
        "mma.sync.aligned.m16n8k16.row.col.f32.bf16.bf16.f32 "
        "{%0,%1,%2,%3}, {%4,%5,%6,%7}, {%8,%9}, {%0,%1,%2,%3};\n"
        : "+f"(c[0]), "+f"(c[1]), "+f"(c[2]), "+f"(c[3])
        : "r"(a[0]), "r"(a[1]), "r"(a[2]), "r"(a[3]), "r"(b0), "r"(b1));
}
__device__ __forceinline__ void cp_async16(unsigned saddr, const void* g) {
    asm volatile("cp.async.cg.shared.global [%0], [%1], 16;\n"
                 :: "r"(saddr), "l"(g) : "memory");
}
__device__ __forceinline__ void cp_commit() {
    asm volatile("cp.async.commit_group;\n" ::: "memory");
}
template <int N> __device__ __forceinline__ void cp_wait() {
    asm volatile("cp.async.wait_group %0;\n" :: "n"(N) : "memory");
}
__device__ __forceinline__ uint32_t smem_u32(const void* p) {
    uint32_t a;
    asm("{ .reg .u64 t; cvta.to.shared.u64 t, %1; cvt.u32.u64 %0, t; }"
        : "=r"(a) : "l"(p));
    return a;
}

// Grid-wide barrier for an exactly-resident persistent grid.
// Two counters: A = arrivals (spin target), B = departures. The last thread
// through B resets both to zero, leaving all state 0 for the next graph
// replay (deterministic). reset_ctr: also clears the embed steal counter.
__device__ __forceinline__ void grid_barrier(unsigned* A, unsigned* B,
                                             unsigned G, bool reset_ctr) {
    __syncthreads();
    if (threadIdx.x == 0) {
        __threadfence();                       // publish this CTA's writes
        atomicAdd(A, 1u);
        while (*(volatile unsigned*)A < G) __nanosleep(64);
        __threadfence();                       // acquire others' writes
        unsigned t = atomicAdd(B, 1u);
        if (t == G - 1u) {                     // everyone has left the spin
            if (reset_ctr) g_ctr = 0u;
            *A = 0u;
            __threadfence();
            *B = 0u;
        }
    }
    __syncthreads();
}

// ---------------------------------------------------------------------------
// Fused persistent kernel: phase 0 (W convert) -> barrier -> phase 1 (embed,
// streamed preconverted W) -> barrier -> phase 2 (similarity + max/sum).
// grid = 2*SMs, 256 thr, occ 2 => whole grid resident => barriers safe.
// ---------------------------------------------------------------------------
#define AK 72       // A smem k-stride (144B pitch, conflict-free)
#define WP 136      // W smem n-stride (272B pitch, conflict-free)
#define DSTR 136    // sim smem row stride

__global__ __launch_bounds__(256, 2) void fused_kernel(
    const float* __restrict__ qh, const float* __restrict__ dh,
    const float* __restrict__ W, const float* __restrict__ bias,
    float* __restrict__ out)
{
    extern __shared__ char smem[];
    const int tid  = threadIdx.x;
    const int lane = tid & 31, warp = tid >> 5;
    const unsigned G = gridDim.x, cta = blockIdx.x;

    // ================= phase 0: W fp32 -> hi/lo bf16 (once) ================
    {
        unsigned gt = cta * 256u + (unsigned)tid;
        if (gt < (unsigned)(HID * DIM / 4)) {       // 8192 float4s
            float4 v = ((const float4*)W)[gt];
            float vv[4] = { v.x, v.y, v.z, v.w };
            __nv_bfloat16 h[4], l[4];
#pragma unroll
            for (int e = 0; e < 4; e++) {
                h[e] = __float2bfloat16(vv[e]);
                l[e] = __float2bfloat16(vv[e] - __bfloat162float(h[e]));
            }
            *(uint2*)&g_Whi[gt * 4] = *(uint2*)h;
            *(uint2*)&g_Wlo[gt * 4] = *(uint2*)l;
        }
    }
    grid_barrier(&gb1a, &gb1b, G, false);

    // ================= phase 1: embed (work-stealing, W streamed) ==========
    {
        __nv_bfloat16* sWhi = (__nv_bfloat16*)smem;           // 64 x 136
        __nv_bfloat16* sWlo = sWhi + 64 * WP;
        __nv_bfloat16* sAhi = sWlo + 64 * WP;                 // 64 x 72
        __nv_bfloat16* sAlo = sAhi + 64 * AK;
        float* ssp = (float*)(sAlo + 64 * AK);                // [64][4]
        unsigned* s_t = (unsigned*)(ssp + 64 * 4);

        const int wm = warp >> 2, wn = warp & 3;
        const unsigned uWhi = smem_u32(sWhi);
        const unsigned uWlo = smem_u32(sWlo);
        const unsigned uAhi = smem_u32(sAhi);
        const unsigned uAlo = smem_u32(sAlo);

        unsigned aoff[2];
#pragma unroll
        for (int mt = 0; mt < 2; mt++)
            aoff[mt] = (unsigned)((wm * 32 + mt * 16 + (lane & 15)) * AK
                                  + (lane >> 4) * 8) * 2;
        const int bk = (lane & 7) + ((lane >> 3) & 1) * 8;
        const unsigned bnb = (unsigned)(wn * 32 + (lane >> 4) * 8) * 2;
        const int cbase = (lane & 3) * 2;

        for (;;) {
            __syncthreads();               // prior tile smem reads complete
            if (tid == 0) *s_t = atomicAdd(&g_ctr, 1u);
            __syncthreads();
            const unsigned t = *s_t;
            if (t >= N_ETILE) break;

            const int row0 = (int)t * 64;
            const float* src = (row0 < N_QTOK)
                ? (qh + (size_t)row0 * HID)
                : (dh + (size_t)(row0 - N_QTOK) * HID);

            float acc[2][4][4];
#pragma unroll
            for (int mt = 0; mt < 2; mt++)
#pragma unroll
                for (int nt = 0; nt < 4; nt++)
#pragma unroll
                    for (int r = 0; r < 4; r++) acc[mt][nt][r] = 0.f;

            for (int kc = 0; kc < 4; kc++) {
                const int k0 = kc * 64;
                if (kc) __syncthreads();   // prior kc ldsm reads done

                // stream preconverted W chunk (64k x 128n, hi+lo) via cp.async
#pragma unroll
                for (int j = 0; j < 4; j++) {
                    int f = tid + j * 256, r = f >> 4, c8 = f & 15;
                    cp_async16(uWhi + (unsigned)(r * WP + c8 * 8) * 2,
                               g_Whi + (size_t)(k0 + r) * DIM + c8 * 8);
                }
#pragma unroll
                for (int j = 0; j < 4; j++) {
                    int f = tid + j * 256, r = f >> 4, c8 = f & 15;
                    cp_async16(uWlo + (unsigned)(r * WP + c8 * 8) * 2,
                               g_Wlo + (size_t)(k0 + r) * DIM + c8 * 8);
                }
                cp_commit();

                // A chunk: 64 rows x 64 k fp32 -> hi/lo (overlaps W transfer)
#pragma unroll
                for (int j = 0; j < 4; j++) {
                    int f = tid + j * 256, r = f >> 4, cv = f & 15;
                    float4 v = *(const float4*)(src + (size_t)r * HID + k0 + cv * 4);
                    float vv[4] = { v.x, v.y, v.z, v.w };
                    __nv_bfloat16 h[4], l[4];
#pragma unroll
                    for (int e = 0; e < 4; e++) {
                        h[e] = __float2bfloat16(vv[e]);
                        l[e] = __float2bfloat16(vv[e] - __bfloat162float(h[e]));
                    }
                    *(uint2*)&sAhi[r * AK + cv * 4] = *(uint2*)h;
                    *(uint2*)&sAlo[r * AK + cv * 4] = *(uint2*)l;
                }
                cp_wait<0>();
                __syncthreads();

#pragma unroll
                for (int ks = 0; ks < 4; ks++) {
                    uint32_t ah0[4], ah1[4], al0[4], al1[4];
                    ldsm4(ah0[0], ah0[1], ah0[2], ah0[3], uAhi + aoff[0] + ks * 32);
                    ldsm4(ah1[0], ah1[1], ah1[2], ah1[3], uAhi + aoff[1] + ks * 32);
                    ldsm4(al0[0], al0[1], al0[2], al0[3], uAlo + aoff[0] + ks * 32);
                    ldsm4(al1[0], al1[1], al1[2], al1[3], uAlo + aoff[1] + ks * 32);
                    const unsigned be = (unsigned)((ks * 16 + bk) * WP) * 2 + bnb;
                    uint32_t bh0[4], bh1[4], bl0[4], bl1[4];
                    ldsm4t(bh0[0], bh0[1], bh0[2], bh0[3], uWhi + be);
                    ldsm4t(bh1[0], bh1[1], bh1[2], bh1[3], uWhi + be + 32);
                    ldsm4t(bl0[0], bl0[1], bl0[2], bl0[3], uWlo + be);
                    ldsm4t(bl1[0], bl1[1], bl1[2], bl1[3], uWlo + be + 32);

                    mma16816(acc[0][0], ah0, bh0[0], bh0[1]);
                    mma16816(acc[0][0], ah0, bl0[0], bl0[1]);
                    mma16816(acc[0][0], al0, bh0[0], bh0[1]);
                    mma16816(acc[0][1], ah0, bh0[2], bh0[3]);
                    mma16816(acc[0][1], ah0, bl0[2], bl0[3]);
                    mma16816(acc[0][1], al0, bh0[2], bh0[3]);
                    mma16816(acc[0][2], ah0, bh1[0], bh1[1]);
                    mma16816(acc[0][2], ah0, bl1[0], bl1[1]);
                    mma16816(acc[0][2], al0, bh1[0], bh1[1]);
                    mma16816(acc[0][3], ah0, bh1[2], bh1[3]);
                    mma16816(acc[0][3], ah0, bl1[2], bl1[3]);
                    mma16816(acc[0][3], al0, bh1[2], bh1[3]);

                    mma16816(acc[1][0], ah1, bh0[0], bh0[1]);
                    mma16816(acc[1][0], ah1, bl0[0], bl0[1]);
                    mma16816(acc[1][0], al1, bh0[0], bh0[1]);
                    mma16816(acc[1][1], ah1, bh0[2], bh0[3]);
                    mma16816(acc[1][1], ah1, bl0[2], bl0[3]);
                    mma16816(acc[1][1], al1, bh0[2], bh0[3]);
                    mma16816(acc[1][2], ah1, bh1[0], bh1[1]);
                    mma16816(acc[1][2], ah1, bl1[0], bl1[1]);
                    mma16816(acc[1][2], al1, bh1[0], bh1[1]);
                    mma16816(acc[1][3], ah1, bh1[2], bh1[3]);
                    mma16816(acc[1][3], ah1, bl1[2], bl1[3]);
                    mma16816(acc[1][3], al1, bh1[2], bh1[3]);
                }
            }

            // epilogue: bias + partial sum-of-squares (this warp's 32 cols)
#pragma unroll
            for (int mt = 0; mt < 2; mt++) {
                float s0 = 0.f, s1 = 0.f;
#pragma unroll
                for (int nt = 0; nt < 4; nt++) {
                    float2 bv = *(const float2*)(bias + wn * 32 + nt * 8 + cbase);
                    acc[mt][nt][0] += bv.x; acc[mt][nt][1] += bv.y;
                    acc[mt][nt][2] += bv.x; acc[mt][nt][3] += bv.y;
                    s0 += acc[mt][nt][0] * acc[mt][nt][0]
                        + acc[mt][nt][1] * acc[mt][nt][1];
                    s1 += acc[mt][nt][2] * acc[mt][nt][2]
                        + acc[mt][nt][3] * acc[mt][nt][3];
                }
                s0 += __shfl_xor_sync(0xffffffffu, s0, 1);
                s0 += __shfl_xor_sync(0xffffffffu, s0, 2);
                s1 += __shfl_xor_sync(0xffffffffu, s1, 1);
                s1 += __shfl_xor_sync(0xffffffffu, s1, 2);
                if ((lane & 3) == 0) {
                    ssp[(wm * 32 + mt * 16 + (lane >> 2)) * 4 + wn] = s0;
                    ssp[(wm * 32 + mt * 16 + 8 + (lane >> 2)) * 4 + wn] = s1;
                }
            }
            __syncthreads();
#pragma unroll
            for (int mt = 0; mt < 2; mt++) {
                const int r0 = wm * 32 + mt * 16 + (lane >> 2);
                const int r1 = r0 + 8;
                float ss0 = ssp[r0 * 4] + ssp[r0 * 4 + 1]
                          + ssp[r0 * 4 + 2] + ssp[r0 * 4 + 3];
                float ss1 = ssp[r1 * 4] + ssp[r1 * 4 + 1]
                          + ssp[r1 * 4 + 2] + ssp[r1 * 4 + 3];
                float inv0 = 1.f / fmaxf(sqrtf(ss0), 1e-12f);
                float inv1 = 1.f / fmaxf(sqrtf(ss1), 1e-12f);
#pragma unroll
                for (int nt = 0; nt < 4; nt++) {
                    __nv_bfloat162 vA, vB;
                    vA.x = __float2bfloat16(acc[mt][nt][0] * inv0);
                    vA.y = __float2bfloat16(acc[mt][nt][1] * inv0);
                    vB.x = __float2bfloat16(acc[mt][nt][2] * inv1);
                    vB.y = __float2bfloat16(acc[mt][nt][3] * inv1);
                    *(__nv_bfloat162*)(g_emb + (size_t)(row0 + r0) * DIM
                                       + wn * 32 + nt * 8 + cbase) = vA;
                    *(__nv_bfloat162*)(g_emb + (size_t)(row0 + r1) * DIM
                                       + wn * 32 + nt * 8 + cbase) = vB;
                }
            }
        }
    }
    grid_barrier(&gb2a, &gb2b, G, true);   // also resets steal counter

    // ================= phase 2: similarity GEMM + max_t + sum_s ===========
    {
        __nv_bfloat16* sQ = (__nv_bfloat16*)smem;              // 128 x 136
        __nv_bfloat16* sD = sQ + 128 * DSTR;                   // 2 x (128 x 136)
        float* red = (float*)(sD + 2 * 128 * DSTR);            // [2][8][32]

        const int wm = warp >> 1, wn = warp & 1;
        unsigned s = (4096u * cta) / G;
        const unsigned e = (4096u * (cta + 1)) / G;

        const unsigned uQ = smem_u32(sQ);
        const unsigned uD = smem_u32(sD);

        unsigned aoff[2];
#pragma unroll
        for (int mt = 0; mt < 2; mt++) {
            int row = wm * 32 + mt * 16 + (lane & 15);
            int col = (lane >> 4) * 8;
            aoff[mt] = uQ + (unsigned)(row * DSTR + col) * 2;
        }
        unsigned boff[4];
#pragma unroll
        for (int g = 0; g < 4; g++) {
            int row = wn * 64 + g * 16 + (lane & 7) + (lane >> 4) * 8;
            int col = ((lane >> 3) & 1) * 8;
            boff[g] = (unsigned)(row * DSTR + col) * 2;
        }

        while (s < e) {
            const unsigned qg = s >> 7;
            const unsigned seg_e = min(e, (qg + 1) << 7);
            const int n = (int)(seg_e - s);
            const unsigned qb0 = qg * 4;
            const unsigned db_base = s & 127;

            {   // load Q tile for this segment
                const __nv_bfloat16* qsrc = g_emb + (size_t)qg * 128 * DIM;
#pragma unroll
                for (int j = 0; j < 8; j++) {
                    int f = tid + j * 256, r = f >> 4, c8 = f & 15;
                    *(uint4*)(sQ + r * DSTR + c8 * 8) =
                        *(const uint4*)(qsrc + (size_t)r * DIM + c8 * 8);
                }
            }
            {   // prefetch first doc tile of segment into buffer 0
                const __nv_bfloat16* dsrc =
                    g_emb + (size_t)(N_QTOK + db_base * 128) * DIM;
#pragma unroll
                for (int j = 0; j < 8; j++) {
                    int f = tid + j * 256, r = f >> 4, c8 = f & 15;
                    cp_async16(uD + (unsigned)(r * DSTR + c8 * 8) * 2,
                               dsrc + (size_t)r * DIM + c8 * 8);
                }
                cp_commit();
            }

            for (int j = 0; j < n; j++) {
                if (j + 1 < n) {
                    const __nv_bfloat16* dsrc =
                        g_emb + (size_t)(N_QTOK + (db_base + j + 1) * 128) * DIM;
                    const unsigned dst =
                        uD + (unsigned)((j + 1) & 1) * (128 * DSTR * 2);
#pragma unroll
                    for (int t2 = 0; t2 < 8; t2++) {
                        int f = tid + t2 * 256, r = f >> 4, c8 = f & 15;
                        cp_async16(dst + (unsigned)(r * DSTR + c8 * 8) * 2,
                                   dsrc + (size_t)r * DIM + c8 * 8);
                    }
                    cp_commit();
                    cp_wait<1>();
                } else {
                    cp_wait<0>();
                }
                __syncthreads();   // S1: tile j data + Q visible

                if (j >= 1 && tid < 128) {   // finalize unit j-1
                    const int qb = tid >> 5, row = tid & 31;
                    const float* rb = red + ((j - 1) & 1) * 256;
                    float v = fmaxf(rb[(qb * 2) * 32 + row],
                                    rb[(qb * 2 + 1) * 32 + row]);
#pragma unroll
                    for (int off = 16; off >= 1; off >>= 1)
                        v += __shfl_xor_sync(0xffffffffu, v, off);
                    if (lane == 0)
                        out[(size_t)(qb0 + qb) * 128 + (db_base + j - 1)] = v;
                }

                float acc[2][8][4];
#pragma unroll
                for (int mt = 0; mt < 2; mt++)
#pragma unroll
                    for (int t2 = 0; t2 < 8; t2++)
#pragma unroll
                        for (int r = 0; r < 4; r++) acc[mt][t2][r] = 0.f;

                const unsigned dbase = uD + (unsigned)(j & 1) * (128 * DSTR * 2);
#pragma unroll
                for (int ks = 0; ks < 8; ks++) {
                    uint32_t a[2][4], b[4][4];
                    ldsm4(a[0][0], a[0][1], a[0][2], a[0][3], aoff[0] + ks * 32);
                    ldsm4(a[1][0], a[1][1], a[1][2], a[1][3], aoff[1] + ks * 32);
#pragma unroll
                    for (int g = 0; g < 4; g++)
                        ldsm4(b[g][0], b[g][1], b[g][2], b[g][3],
                              dbase + boff[g] + ks * 32);
#pragma unroll
                    for (int mt = 0; mt < 2; mt++)
#pragma unroll
                        for (int t2 = 0; t2 < 8; t2++)
                            mma16816(acc[mt][t2], a[mt],
                                     b[t2 >> 1][(t2 & 1) * 2],
                                     b[t2 >> 1][(t2 & 1) * 2 + 1]);
                }

                // in-warp row-max over this warp's 64 columns -> red[j&1]
                float* rw = red + (j & 1) * 256 + warp * 32;
#pragma unroll
                for (int mt = 0; mt < 2; mt++) {
#pragma unroll
                    for (int h = 0; h < 2; h++) {
                        float m = -3.4e38f;
#pragma unroll
                        for (int t2 = 0; t2 < 8; t2++)
                            m = fmaxf(m, fmaxf(acc[mt][t2][2 * h],
                                               acc[mt][t2][2 * h + 1]));
                        m = fmaxf(m, __shfl_xor_sync(0xffffffffu, m, 1));
                        m = fmaxf(m, __shfl_xor_sync(0xffffffffu, m, 2));
                        if ((lane & 3) == 0)
                            rw[mt * 16 + h * 8 + (lane >> 2)] = m;
                    }
                }
                __syncthreads();   // S2: red complete; buffers reusable
            }

            // tail: finalize last unit of segment
            if (tid < 128) {
                const int qb = tid >> 5, row = tid & 31;
                const float* rb = red + ((n - 1) & 1) * 256;
                float v = fmaxf(rb[(qb * 2) * 32 + row],
                                rb[(qb * 2 + 1) * 32 + row]);
#pragma unroll
                for (int off = 16; off >= 1; off >>= 1)
                    v += __shfl_xor_sync(0xffffffffu, v, off);
                if (lane == 0)
                    out[(size_t)(qb0 + qb) * 128 + (db_base + n - 1)] = v;
            }
            __syncthreads();
            s = seg_e;
        }
    }
}

// ---------------------------------------------------------------------------
extern "C" void kernel_launch(void* const* d_in, const int* in_sizes, int n_in,
                              void* d_out, int out_size) {
    const float* qh   = (const float*)d_in[0];
    const float* dh   = (const float*)d_in[1];
    const float* W    = (const float*)d_in[2];
    const float* bias = (const float*)d_in[3];
    float* out = (float*)d_out;

    int sms = 148;
    cudaDeviceGetAttribute(&sms, cudaDevAttrMultiProcessorCount, 0);

    // smem = max(phase1 ~55KB, phase2 106.5KB)
    const int SMEM = 3 * 128 * DSTR * 2 + 2 * 256 * 4;   // 106496
    cudaFuncSetAttribute(fused_kernel,
                         cudaFuncAttributeMaxDynamicSharedMemorySize, SMEM);

    fused_kernel<<<2 * sms, 256, SMEM>>>(qh, dh, W, bias, out);
}

// round 11
// speedup vs baseline: 1.0451x; 1.0451x over previous
#include <cuda_runtime.h>
#include <cuda_bf16.h>
#include <cstdint>
#include <cstddef>

#define N_QTOK 4096      // 128 query batches * 32 tokens
#define N_DTOK 16384     // 128 doc batches * 128 tokens
#define N_TOK  20480
#define DIM    128
#define HID    256
#define N_ETILE 320      // 20480 / 64 rows per embed tile

// bf16 normalized embeddings: rows 0..4095 = query tokens, 4096..20479 = doc
__device__ __align__(16) __nv_bfloat16 g_emb[(size_t)N_TOK * DIM];
__device__ unsigned g_ctr;   // embed steal counter; reset by sim_kernel

// ---------------------------------------------------------------------------
// PTX helpers (base sm_103 only — tcgen05 needs compute_103a virtual arch,
// which the harness does not use)
// ---------------------------------------------------------------------------
__device__ __forceinline__ void ldsm4(uint32_t& r0, uint32_t& r1,
                                      uint32_t& r2, uint32_t& r3, unsigned addr) {
    asm volatile("ldmatrix.sync.aligned.m8n8.x4.shared.b16 {%0,%1,%2,%3}, [%4];\n"
                 : "=r"(r0), "=r"(r1), "=r"(r2), "=r"(r3) : "r"(addr));
}
__device__ __forceinline__ void ldsm4t(uint32_t& r0, uint32_t& r1,
                                       uint32_t& r2, uint32_t& r3, unsigned addr) {
    asm volatile("ldmatrix.sync.aligned.m8n8.x4.trans.shared.b16 {%0,%1,%2,%3}, [%4];\n"
                 : "=r"(r0), "=r"(r1), "=r"(r2), "=r"(r3) : "r"(addr));
}
__device__ __forceinline__ void mma16816(float* c, const uint32_t* a,
                                         uint32_t b0, uint32_t b1) {
    asm volatile(
        "mma.sync.aligned.m16n8k16.row.col.f32.bf16.bf16.f32 "
        "{%0,%1,%2,%3}, {%4,%5,%6,%7}, {%8,%9}, {%0,%1,%2,%3};\n"
        : "+f"(c[0]), "+f"(c[1]), "+f"(c[2]), "+f"(c[3])
        : "r"(a[0]), "r"(a[1]), "r"(a[2]), "r"(a[3]), "r"(b0), "r"(b1));
}
__device__ __forceinline__ void cp_async16(unsigned saddr, const void* g) {
    asm volatile("cp.async.cg.shared.global [%0], [%1], 16;\n"
                 :: "r"(saddr), "l"(g) : "memory");
}
__device__ __forceinline__ void cp_commit() {
    asm volatile("cp.async.commit_group;\n" ::: "memory");
}
template <int N> __device__ __forceinline__ void cp_wait() {
    asm volatile("cp.async.wait_group %0;\n" :: "n"(N) : "memory");
}
__device__ __forceinline__ uint32_t smem_u32(const void* p) {
    uint32_t a;
    asm("{ .reg .u64 t; cvta.to.shared.u64 t, %1; cvt.u32.u64 %0, t; }"
        : "=r"(a) : "l"(p));
    return a;
}
__device__ __forceinline__ void cvt_hilo4(const float4& v,
                                          __nv_bfloat16* h, __nv_bfloat16* l) {
    float vv[4] = { v.x, v.y, v.z, v.w };
#pragma unroll
    for (int e = 0; e < 4; e++) {
        h[e] = __float2bfloat16(vv[e]);
        l[e] = __float2bfloat16(vv[e] - __bfloat162float(h[e]));
    }
}

// ---------------------------------------------------------------------------
// Kernel 1: projection + bias + L2 normalize (hi/lo bf16 split ~ fp32).
// Work-stealing 320 tiles x 64 rows; grid = 2*SMs, occ 2.
// Block 256 thr / 8 warps as 2(M) x 4(N): warp tile 32 x 32.
// kc PIPELINE: smem double-buffered W+A chunks; fp32 LDG of chunk kc+1 is
// issued before the mma block on chunk kc (latency hidden), convert+STS
// into the other buffer after; one __syncthreads per kc.
// ---------------------------------------------------------------------------
#define AK 72       // A smem k-stride (144B pitch, conflict-free)
#define WP 136      // W smem n-stride (272B pitch, conflict-free)
// per-buffer element counts (bf16)
#define WB_ELEM (64 * WP)            // 8704 per hi or lo
#define AB_ELEM (64 * AK)            // 4608 per hi or lo
#define BUF_ELEM (2 * WB_ELEM + 2 * AB_ELEM)   // 26624

__global__ __launch_bounds__(256, 2) void embed_kernel(
    const float* __restrict__ qh, const float* __restrict__ dh,
    const float* __restrict__ W, const float* __restrict__ bias)
{
    extern __shared__ char esm[];
    __nv_bfloat16* sb16 = (__nv_bfloat16*)esm;   // [2][BUF_ELEM]
    float* ssp = (float*)(esm + 2 * BUF_ELEM * 2);        // [64][4]
    unsigned* s_t = (unsigned*)(ssp + 64 * 4);

    const int tid  = threadIdx.x;
    const int lane = tid & 31, warp = tid >> 5;
    const int wm = warp >> 2, wn = warp & 3;

    // buffer base addresses (smem u32)
    unsigned uWhi[2], uWlo[2], uAhi[2], uAlo[2];
#pragma unroll
    for (int b = 0; b < 2; b++) {
        unsigned base = smem_u32(sb16 + (size_t)b * BUF_ELEM);
        uWhi[b] = base;
        uWlo[b] = base + WB_ELEM * 2;
        uAhi[b] = base + 2 * WB_ELEM * 2;
        uAlo[b] = base + (2 * WB_ELEM + AB_ELEM) * 2;
    }

    unsigned aoff[2];
#pragma unroll
    for (int mt = 0; mt < 2; mt++)
        aoff[mt] = (unsigned)((wm * 32 + mt * 16 + (lane & 15)) * AK
                              + (lane >> 4) * 8) * 2;
    const int bk = (lane & 7) + ((lane >> 3) & 1) * 8;
    const unsigned bnb = (unsigned)(wn * 32 + (lane >> 4) * 8) * 2;
    const int cbase = (lane & 3) * 2;

    // per-thread load coordinates
    const int wr = tid >> 3 /*unused*/, dummy = wr;
    (void)dummy;

    for (;;) {
        __syncthreads();               // prior tile smem reads complete
        if (tid == 0) *s_t = atomicAdd(&g_ctr, 1u);
        __syncthreads();
        const unsigned t = *s_t;
        if (t >= N_ETILE) break;

        const int row0 = (int)t * 64;
        const float* src = (row0 < N_QTOK)
            ? (qh + (size_t)row0 * HID)
            : (dh + (size_t)(row0 - N_QTOK) * HID);

        // ---- prologue: load + convert kc=0 into buffer 0
        {
#pragma unroll
            for (int j = 0; j < 8; j++) {       // W: 64k x 128n
                int f = tid + j * 256, r = f >> 5, c4 = f & 31;
                float4 v = *(const float4*)(W + (size_t)r * DIM + c4 * 4);
                __nv_bfloat16 h[4], l[4];
                cvt_hilo4(v, h, l);
                unsigned off = (unsigned)(r * WP + c4 * 4) * 2;
                *(uint2*)(esm + uWhi[0] - smem_u32(esm) + off) = *(uint2*)h;
                *(uint2*)(esm + uWlo[0] - smem_u32(esm) + off) = *(uint2*)l;
            }
#pragma unroll
            for (int j = 0; j < 4; j++) {       // A: 64 rows x 64 k
                int f = tid + j * 256, r = f >> 4, cv = f & 15;
                float4 v = *(const float4*)(src + (size_t)r * HID + cv * 4);
                __nv_bfloat16 h[4], l[4];
                cvt_hilo4(v, h, l);
                unsigned off = (unsigned)(r * AK + cv * 4) * 2;
                *(uint2*)(esm + uAhi[0] - smem_u32(esm) + off) = *(uint2*)h;
                *(uint2*)(esm + uAlo[0] - smem_u32(esm) + off) = *(uint2*)l;
            }
        }
        __syncthreads();

        float acc[2][4][4];
#pragma unroll
        for (int mt = 0; mt < 2; mt++)
#pragma unroll
            for (int nt = 0; nt < 4; nt++)
#pragma unroll
                for (int r = 0; r < 4; r++) acc[mt][nt][r] = 0.f;

#pragma unroll
        for (int kc = 0; kc < 4; kc++) {
            const int cb = kc & 1, nb = cb ^ 1;

            // prefetch fp32 chunk kc+1 into registers (hidden behind mma)
            float4 wreg[8], areg[4];
            if (kc < 3) {
                const int k0n = (kc + 1) * 64;
#pragma unroll
                for (int j = 0; j < 8; j++) {
                    int f = tid + j * 256, r = f >> 5, c4 = f & 31;
                    wreg[j] = *(const float4*)(W + (size_t)(k0n + r) * DIM + c4 * 4);
                }
#pragma unroll
                for (int j = 0; j < 4; j++) {
                    int f = tid + j * 256, r = f >> 4, cv = f & 15;
                    areg[j] = *(const float4*)(src + (size_t)r * HID + k0n + cv * 4);
                }
            }

            // mma over buffer cb
#pragma unroll
            for (int ks = 0; ks < 4; ks++) {
                uint32_t ah0[4], ah1[4], al0[4], al1[4];
                ldsm4(ah0[0], ah0[1], ah0[2], ah0[3], uAhi[cb] + aoff[0] + ks * 32);
                ldsm4(ah1[0], ah1[1], ah1[2], ah1[3], uAhi[cb] + aoff[1] + ks * 32);
                ldsm4(al0[0], al0[1], al0[2], al0[3], uAlo[cb] + aoff[0] + ks * 32);
                ldsm4(al1[0], al1[1], al1[2], al1[3], uAlo[cb] + aoff[1] + ks * 32);
                const unsigned be = (unsigned)((ks * 16 + bk) * WP) * 2 + bnb;
                uint32_t bh0[4], bh1[4], bl0[4], bl1[4];
                ldsm4t(bh0[0], bh0[1], bh0[2], bh0[3], uWhi[cb] + be);
                ldsm4t(bh1[0], bh1[1], bh1[2], bh1[3], uWhi[cb] + be + 32);
                ldsm4t(bl0[0], bl0[1], bl0[2], bl0[3], uWlo[cb] + be);
                ldsm4t(bl1[0], bl1[1], bl1[2], bl1[3], uWlo[cb] + be + 32);

                mma16816(acc[0][0], ah0, bh0[0], bh0[1]);
                mma16816(acc[0][0], ah0, bl0[0], bl0[1]);
                mma16816(acc[0][0], al0, bh0[0], bh0[1]);
                mma16816(acc[0][1], ah0, bh0[2], bh0[3]);
                mma16816(acc[0][1], ah0, bl0[2], bl0[3]);
                mma16816(acc[0][1], al0, bh0[2], bh0[3]);
                mma16816(acc[0][2], ah0, bh1[0], bh1[1]);
                mma16816(acc[0][2], ah0, bl1[0], bl1[1]);
                mma16816(acc[0][2], al0, bh1[0], bh1[1]);
                mma16816(acc[0][3], ah0, bh1[2], bh1[3]);
                mma16816(acc[0][3], ah0, bl1[2], bl1[3]);
                mma16816(acc[0][3], al0, bh1[2], bh1[3]);

                mma16816(acc[1][0], ah1, bh0[0], bh0[1]);
                mma16816(acc[1][0], ah1, bl0[0], bl0[1]);
                mma16816(acc[1][0], al1, bh0[0], bh0[1]);
                mma16816(acc[1][1], ah1, bh0[2], bh0[3]);
                mma16816(acc[1][1], ah1, bl0[2], bl0[3]);
                mma16816(acc[1][1], al1, bh0[2], bh0[3]);
                mma16816(acc[1][2], ah1, bh1[0], bh1[1]);
                mma16816(acc[1][2], ah1, bl1[0], bl1[1]);
                mma16816(acc[1][2], al1, bh1[0], bh1[1]);
                mma16816(acc[1][3], ah1, bh1[2], bh1[3]);
                mma16816(acc[1][3], ah1, bl1[2], bl1[3]);
                mma16816(acc[1][3], al1, bh1[2], bh1[3]);
            }

            // convert + store chunk kc+1 into the other buffer
            if (kc < 3) {
#pragma unroll
                for (int j = 0; j < 8; j++) {
                    int f = tid + j * 256, r = f >> 5, c4 = f & 31;
                    __nv_bfloat16 h[4], l[4];
                    cvt_hilo4(wreg[j], h, l);
                    unsigned off = (unsigned)(r * WP + c4 * 4) * 2;
                    asm volatile("st.shared.v2.b32 [%0], {%1, %2};\n" ::
                        "r"(uWhi[nb] + off),
                        "r"(*(uint32_t*)&h[0]), "r"(*(uint32_t*)&h[2]));
                    asm volatile("st.shared.v2.b32 [%0], {%1, %2};\n" ::
                        "r"(uWlo[nb] + off),
                        "r"(*(uint32_t*)&l[0]), "r"(*(uint32_t*)&l[2]));
                }
#pragma unroll
                for (int j = 0; j < 4; j++) {
                    int f = tid + j * 256, r = f >> 4, cv = f & 15;
                    __nv_bfloat16 h[4], l[4];
                    cvt_hilo4(areg[j], h, l);
                    unsigned off = (unsigned)(r * AK + cv * 4) * 2;
                    asm volatile("st.shared.v2.b32 [%0], {%1, %2};\n" ::
                        "r"(uAhi[nb] + off),
                        "r"(*(uint32_t*)&h[0]), "r"(*(uint32_t*)&h[2]));
                    asm volatile("st.shared.v2.b32 [%0], {%1, %2};\n" ::
                        "r"(uAlo[nb] + off),
                        "r"(*(uint32_t*)&l[0]), "r"(*(uint32_t*)&l[2]));
                }
            }
            __syncthreads();   // STS(nb) visible + ldsm(cb) done
        }

        // epilogue: bias + partial sum-of-squares (this warp's 32 cols)
#pragma unroll
        for (int mt = 0; mt < 2; mt++) {
            float s0 = 0.f, s1 = 0.f;
#pragma unroll
            for (int nt = 0; nt < 4; nt++) {
                float2 bv = *(const float2*)(bias + wn * 32 + nt * 8 + cbase);
                acc[mt][nt][0] += bv.x; acc[mt][nt][1] += bv.y;
                acc[mt][nt][2] += bv.x; acc[mt][nt][3] += bv.y;
                s0 += acc[mt][nt][0] * acc[mt][nt][0]
                    + acc[mt][nt][1] * acc[mt][nt][1];
                s1 += acc[mt][nt][2] * acc[mt][nt][2]
                    + acc[mt][nt][3] * acc[mt][nt][3];
            }
            s0 += __shfl_xor_sync(0xffffffffu, s0, 1);
            s0 += __shfl_xor_sync(0xffffffffu, s0, 2);
            s1 += __shfl_xor_sync(0xffffffffu, s1, 1);
            s1 += __shfl_xor_sync(0xffffffffu, s1, 2);
            if ((lane & 3) == 0) {
                ssp[(wm * 32 + mt * 16 + (lane >> 2)) * 4 + wn] = s0;
                ssp[(wm * 32 + mt * 16 + 8 + (lane >> 2)) * 4 + wn] = s1;
            }
        }
        __syncthreads();
#pragma unroll
        for (int mt = 0; mt < 2; mt++) {
            const int r0 = wm * 32 + mt * 16 + (lane >> 2);
            const int r1 = r0 + 8;
            float ss0 = ssp[r0 * 4] + ssp[r0 * 4 + 1]
                      + ssp[r0 * 4 + 2] + ssp[r0 * 4 + 3];
            float ss1 = ssp[r1 * 4] + ssp[r1 * 4 + 1]
                      + ssp[r1 * 4 + 2] + ssp[r1 * 4 + 3];
            float inv0 = 1.f / fmaxf(sqrtf(ss0), 1e-12f);
            float inv1 = 1.f / fmaxf(sqrtf(ss1), 1e-12f);
#pragma unroll
            for (int nt = 0; nt < 4; nt++) {
                __nv_bfloat162 vA, vB;
                vA.x = __float2bfloat16(acc[mt][nt][0] * inv0);
                vA.y = __float2bfloat16(acc[mt][nt][1] * inv0);
                vB.x = __float2bfloat16(acc[mt][nt][2] * inv1);
                vB.y = __float2bfloat16(acc[mt][nt][3] * inv1);
                *(__nv_bfloat162*)(g_emb + (size_t)(row0 + r0) * DIM
                                   + wn * 32 + nt * 8 + cbase) = vA;
                *(__nv_bfloat162*)(g_emb + (size_t)(row0 + r1) * DIM
                                   + wn * 32 + nt * 8 + cbase) = vB;
            }
        }
    }
}

// ---------------------------------------------------------------------------
// Kernel 2: PERSISTENT fused similarity GEMM + max_t + sum_s (unchanged R9;
// resets g_ctr for the next graph replay).
// ---------------------------------------------------------------------------
#define DSTR 136

__global__ __launch_bounds__(256, 2) void sim_kernel(float* __restrict__ out)
{
    extern __shared__ char smem[];
    __nv_bfloat16* sQ = (__nv_bfloat16*)smem;              // 128 x 136
    __nv_bfloat16* sD = sQ + 128 * DSTR;                   // 2 x (128 x 136)
    float* red = (float*)(sD + 2 * 128 * DSTR);            // [2][8 warps][32]

    const int tid  = threadIdx.x;
    const int lane = tid & 31, warp = tid >> 5;
    const int wm = warp >> 1, wn = warp & 1;
    const unsigned G = gridDim.x, c = blockIdx.x;
    unsigned s = (4096u * c) / G;
    const unsigned e = (4096u * (c + 1)) / G;

    if (c == 0 && tid == 0) g_ctr = 0u;   // reset embed steal counter

    const unsigned uQ = smem_u32(sQ);
    const unsigned uD = smem_u32(sD);

    unsigned aoff[2];
#pragma unroll
    for (int mt = 0; mt < 2; mt++) {
        int row = wm * 32 + mt * 16 + (lane & 15);
        int col = (lane >> 4) * 8;
        aoff[mt] = uQ + (unsigned)(row * DSTR + col) * 2;
    }
    unsigned boff[4];
#pragma unroll
    for (int g = 0; g < 4; g++) {
        int row = wn * 64 + g * 16 + (lane & 7) + (lane >> 4) * 8;
        int col = ((lane >> 3) & 1) * 8;
        boff[g] = (unsigned)(row * DSTR + col) * 2;
    }

    while (s < e) {
        const unsigned qg = s >> 7;
        const unsigned seg_e = min(e, (qg + 1) << 7);
        const int n = (int)(seg_e - s);
        const unsigned qb0 = qg * 4;
        const unsigned db_base = s & 127;

        {   // load Q tile for this segment
            const __nv_bfloat16* qsrc = g_emb + (size_t)qg * 128 * DIM;
#pragma unroll
            for (int j = 0; j < 8; j++) {
                int f = tid + j * 256, r = f >> 4, c8 = f & 15;
                *(uint4*)(sQ + r * DSTR + c8 * 8) =
                    *(const uint4*)(qsrc + (size_t)r * DIM + c8 * 8);
            }
        }
        {   // prefetch first doc tile of segment into buffer 0
            const __nv_bfloat16* dsrc =
                g_emb + (size_t)(N_QTOK + db_base * 128) * DIM;
#pragma unroll
            for (int j = 0; j < 8; j++) {
                int f = tid + j * 256, r = f >> 4, c8 = f & 15;
                cp_async16(uD + (unsigned)(r * DSTR + c8 * 8) * 2,
                           dsrc + (size_t)r * DIM + c8 * 8);
            }
            cp_commit();
        }

        for (int j = 0; j < n; j++) {
            if (j + 1 < n) {
                const __nv_bfloat16* dsrc =
                    g_emb + (size_t)(N_QTOK + (db_base + j + 1) * 128) * DIM;
                const unsigned dst =
                    uD + (unsigned)((j + 1) & 1) * (128 * DSTR * 2);
#pragma unroll
                for (int t = 0; t < 8; t++) {
                    int f = tid + t * 256, r = f >> 4, c8 = f & 15;
                    cp_async16(dst + (unsigned)(r * DSTR + c8 * 8) * 2,
                               dsrc + (size_t)r * DIM + c8 * 8);
                }
                cp_commit();
                cp_wait<1>();
            } else {
                cp_wait<0>();
            }
            __syncthreads();   // S1: tile j data + Q visible

            if (j >= 1 && tid < 128) {   // finalize unit j-1
                const int qb = tid >> 5, row = tid & 31;
                const float* rb = red + ((j - 1) & 1) * 256;
                float v = fmaxf(rb[(qb * 2) * 32 + row],
                                rb[(qb * 2 + 1) * 32 + row]);
#pragma unroll
                for (int off = 16; off >= 1; off >>= 1)
                    v += __shfl_xor_sync(0xffffffffu, v, off);
                if (lane == 0)
                    out[(size_t)(qb0 + qb) * 128 + (db_base + j - 1)] = v;
            }

            float acc[2][8][4];
#pragma unroll
            for (int mt = 0; mt < 2; mt++)
#pragma unroll
                for (int t = 0; t < 8; t++)
#pragma unroll
                    for (int r = 0; r < 4; r++) acc[mt][t][r] = 0.f;

            const unsigned dbase = uD + (unsigned)(j & 1) * (128 * DSTR * 2);
#pragma unroll
            for (int ks = 0; ks < 8; ks++) {
                uint32_t a[2][4], b[4][4];
                ldsm4(a[0][0], a[0][1], a[0][2], a[0][3], aoff[0] + ks * 32);
                ldsm4(a[1][0], a[1][1], a[1][2], a[1][3], aoff[1] + ks * 32);
#pragma unroll
                for (int g = 0; g < 4; g++)
                    ldsm4(b[g][0], b[g][1], b[g][2], b[g][3],
                          dbase + boff[g] + ks * 32);
#pragma unroll
                for (int mt = 0; mt < 2; mt++)
#pragma unroll
                    for (int t = 0; t < 8; t++)
                        mma16816(acc[mt][t], a[mt],
                                 b[t >> 1][(t & 1) * 2],
                                 b[t >> 1][(t & 1) * 2 + 1]);
            }

            // in-warp row-max over this warp's 64 columns -> red[j&1]
            float* rw = red + (j & 1) * 256 + warp * 32;
#pragma unroll
            for (int mt = 0; mt < 2; mt++) {
#pragma unroll
                for (int h = 0; h < 2; h++) {
                    float m = -3.4e38f;
#pragma unroll
                    for (int t = 0; t < 8; t++)
                        m = fmaxf(m, fmaxf(acc[mt][t][2 * h],
                                           acc[mt][t][2 * h + 1]));
                    m = fmaxf(m, __shfl_xor_sync(0xffffffffu, m, 1));
                    m = fmaxf(m, __shfl_xor_sync(0xffffffffu, m, 2));
                    if ((lane & 3) == 0)
                        rw[mt * 16 + h * 8 + (lane >> 2)] = m;
                }
            }
            __syncthreads();   // S2: red complete; buffers reusable
        }

        // tail: finalize last unit of segment
        if (tid < 128) {
            const int qb = tid >> 5, row = tid & 31;
            const float* rb = red + ((n - 1) & 1) * 256;
            float v = fmaxf(rb[(qb * 2) * 32 + row],
                            rb[(qb * 2 + 1) * 32 + row]);
#pragma unroll
            for (int off = 16; off >= 1; off >>= 1)
                v += __shfl_xor_sync(0xffffffffu, v, off);
            if (lane == 0)
                out[(size_t)(qb0 + qb) * 128 + (db_base + n - 1)] = v;
        }
        __syncthreads();
        s = seg_e;
    }
}

// ---------------------------------------------------------------------------
extern "C" void kernel_launch(void* const* d_in, const int* in_sizes, int n_in,
                              void* d_out, int out_size) {
    const float* qh   = (const float*)d_in[0];
    const float* dh   = (const float*)d_in[1];
    const float* W    = (const float*)d_in[2];
    const float* bias = (const float*)d_in[3];
    float* out = (float*)d_out;

    int sms = 148;
    cudaDeviceGetAttribute(&sms, cudaDevAttrMultiProcessorCount, 0);

    const int ESMEM = 2 * BUF_ELEM * 2 + 64 * 4 * 4 + 16;  // 106496+1024+16
    const int SSMEM = 3 * 128 * DSTR * 2 + 2 * 256 * 4;    // 106496
    cudaFuncSetAttribute(embed_kernel,
                         cudaFuncAttributeMaxDynamicSharedMemorySize, ESMEM);
    cudaFuncSetAttribute(sim_kernel,
                         cudaFuncAttributeMaxDynamicSharedMemorySize, SSMEM);

    embed_kernel<<<2 * sms, 256, ESMEM>>>(qh, dh, W, bias);
    sim_kernel<<<2 * sms, 256, SSMEM>>>(out);
}